// round 17
// baseline (speedup 1.0000x reference)
#include <cuda_runtime.h>

#define NL 8192
#define NC 16384
#define BD 256
#define DD 64
#define SLOPE 0.01f
#define LCAP 64
#define SCAPC 40

#define OUT_L 0
#define OUT_C 2097152
#define OUT_U 6291456

#define FUSED_BLOCKS (NC / 16)    // 1024: scan 16 rows + clause update
#define PB_BLOCKS    (NL / 16)    // 512: P tiles
#define MEGA2_BLOCKS (FUSED_BLOCKS + PB_BLOCKS)   // 1536

// ---------------- device scratch ----------------
__device__ float g_LT[(size_t)NL * BD];      // L_t node-major
__device__ float g_CnewT[(size_t)NC * BD];   // C_new node-major
__device__ float g_P[(size_t)NL * BD];       // WLu1@L + WLu3@Lflip + bLu
__device__ int   g_litCnt[NL];
__device__ int   g_litList[(size_t)NL * LCAP];
__device__ float g_Wcm[DD * DD];   // WCu2 @ WLmsg
__device__ float g_Wcl[DD * DD];   // WLu2 @ WCmsg
__device__ float g_bcm[DD];
__device__ float g_bcl[DD];
__device__ float g_sumL[BD];
__device__ float g_sumC[BD];

__device__ __forceinline__ float leaky(float x) { return x >= 0.f ? x : SLOPE * x; }

// acc2[8] (packed f32x2 pairs) += {w,w} * x[0..15]
#define FMA16P(acc2, wf, xptr) do {                                              \
    unsigned long long _w2;                                                      \
    asm("mov.b64 %0, {%1, %1};" : "=l"(_w2) : "f"(wf));                          \
    const ulonglong2* _x = (const ulonglong2*)(xptr);                            \
    ulonglong2 _p0 = _x[0]; ulonglong2 _p1 = _x[1];                              \
    ulonglong2 _p2 = _x[2]; ulonglong2 _p3 = _x[3];                              \
    asm("fma.rn.f32x2 %0, %1, %2, %0;" : "+l"(acc2[0]) : "l"(_w2), "l"(_p0.x));  \
    asm("fma.rn.f32x2 %0, %1, %2, %0;" : "+l"(acc2[1]) : "l"(_w2), "l"(_p0.y));  \
    asm("fma.rn.f32x2 %0, %1, %2, %0;" : "+l"(acc2[2]) : "l"(_w2), "l"(_p1.x));  \
    asm("fma.rn.f32x2 %0, %1, %2, %0;" : "+l"(acc2[3]) : "l"(_w2), "l"(_p1.y));  \
    asm("fma.rn.f32x2 %0, %1, %2, %0;" : "+l"(acc2[4]) : "l"(_w2), "l"(_p2.x));  \
    asm("fma.rn.f32x2 %0, %1, %2, %0;" : "+l"(acc2[5]) : "l"(_w2), "l"(_p2.y));  \
    asm("fma.rn.f32x2 %0, %1, %2, %0;" : "+l"(acc2[6]) : "l"(_w2), "l"(_p3.x));  \
    asm("fma.rn.f32x2 %0, %1, %2, %0;" : "+l"(acc2[7]) : "l"(_w2), "l"(_p3.y));  \
} while (0)

#define UNPACK16(acc, acc2)                                                       \
    _Pragma("unroll")                                                             \
    for (int _k = 0; _k < 8; _k++)                                                \
        asm("mov.b64 {%0, %1}, %2;" : "=f"(acc[2*_k]), "=f"(acc[2*_k+1]) : "l"(acc2[_k]));

// ---------------- kernels ----------------

// zero counters + combine folded weights
__global__ void k_zero(const float* __restrict__ WCu, const float* __restrict__ WLmsg,
                       const float* __restrict__ bLmsg, const float* __restrict__ WLu,
                       const float* __restrict__ WCmsg, const float* __restrict__ bCmsg) {
    int i = blockIdx.x * 256 + threadIdx.x;
    if (i < NL) g_litCnt[i] = 0;
    if (i < BD) { g_sumL[i] = 0.f; g_sumC[i] = 0.f; }
    if (i < 4096) {
        int o = i >> 6, c = i & 63;
        float s = 0.f;
        #pragma unroll
        for (int j = 0; j < 64; j++) s += WCu[o * 128 + 64 + j] * WLmsg[j * 64 + c];
        g_Wcm[i] = s;
    } else if (i < 8192) {
        int k = i - 4096;
        int o = k >> 6, c = k & 63;
        float s = 0.f;
        #pragma unroll
        for (int j = 0; j < 64; j++) s += WLu[o * 192 + 64 + j] * WCmsg[j * 64 + c];
        g_Wcl[k] = s;
    } else if (i < 8256) {
        int o = i - 8192;
        float s = 0.f;
        #pragma unroll
        for (int j = 0; j < 64; j++) s += WCu[o * 128 + 64 + j] * bLmsg[j];
        g_bcm[o] = s;
    } else if (i < 8320) {
        int o = i - 8256;
        float s = 0.f;
        #pragma unroll
        for (int j = 0; j < 64; j++) s += WLu[o * 192 + 64 + j] * bCmsg[j];
        g_bcl[o] = s;
    }
}

// transpose L_t [256][NL] -> g_LT [NL][256]
__global__ __launch_bounds__(256) void k_prep(const float* __restrict__ L) {
    __shared__ float s[256 * 33];
    int tid = threadIdx.x;
    int l0 = blockIdx.x * 32;
    for (int idx = tid; idx < 256 * 32; idx += 256) {
        int r = idx >> 5, c = idx & 31;
        s[r * 33 + c] = L[(size_t)r * NL + l0 + c];
    }
    __syncthreads();
    #pragma unroll
    for (int li = 0; li < 32; li++)
        g_LT[(size_t)(l0 + li) * BD + tid] = s[tid * 33 + li];
}

// Mega2: fused row-scan + clause update | P tiles, Bresenham-interleaved.
__global__ __launch_bounds__(256) void k_mega2(const uint4* __restrict__ A4,
                                               const float* __restrict__ L,
                                               const float* __restrict__ C,
                                               const float* __restrict__ WCu,
                                               const float* __restrict__ WLu,
                                               const float* __restrict__ bCu,
                                               const float* __restrict__ bLu,
                                               float* __restrict__ outC) {
    __shared__ float smem_buf[256 * 40 + 16 + 16 * SCAPC + 16];   // ~43.6KB
    int bid = blockIdx.x;
    int tid = threadIdx.x;

    int f_lo = (int)(((long long)bid * FUSED_BLOCKS) / MEGA2_BLOCKS);
    int f_hi = (int)(((long long)(bid + 1) * FUSED_BLOCKS) / MEGA2_BLOCKS);
    bool is_fused = (f_hi > f_lo);
    int fused_id = f_lo;
    int p_id = bid - f_lo;

    if (is_fused) {
        float* s_ct  = smem_buf;                    // 256*20
        float* s_S   = s_ct + 256 * 20;             // 256*20
        int*   s_cnt = (int*)(s_S + 256 * 20);      // 16
        int*   s_list = s_cnt + 16;                 // 16*SCAPC

        int c0 = fused_id * 16;

        for (int idx = tid; idx < 256 * 16; idx += 256) {
            int r = idx >> 4, cc = idx & 15;
            s_ct[r * 20 + cc] = C[(size_t)r * NC + c0 + cc];
        }
        if (tid < 16) s_cnt[tid] = 0;
        __syncthreads();

        // scan 16 contiguous clause rows; lists land in smem (clause) + gmem (literal)
        #pragma unroll 1
        for (int r = 0; r < 16; r++) {
            const uint4* row = A4 + (size_t)(c0 + r) * (NL / 4);
            uint4 v0 = __ldcs(&row[tid]);
            uint4 v1 = __ldcs(&row[tid + 256]);
            uint4 v2 = __ldcs(&row[tid + 512]);
            uint4 v3 = __ldcs(&row[tid + 768]);
            uint4 v4 = __ldcs(&row[tid + 1024]);
            uint4 v5 = __ldcs(&row[tid + 1280]);
            uint4 v6 = __ldcs(&row[tid + 1536]);
            uint4 v7 = __ldcs(&row[tid + 1792]);
            unsigned any = (v0.x | v0.y | v0.z | v0.w) | (v1.x | v1.y | v1.z | v1.w)
                         | (v2.x | v2.y | v2.z | v2.w) | (v3.x | v3.y | v3.z | v3.w)
                         | (v4.x | v4.y | v4.z | v4.w) | (v5.x | v5.y | v5.z | v5.w)
                         | (v6.x | v6.y | v6.z | v6.w) | (v7.x | v7.y | v7.z | v7.w);
            if (any) {
                uint4 vv[8] = {v0, v1, v2, v3, v4, v5, v6, v7};
                #pragma unroll
                for (int k = 0; k < 8; k++) {
                    uint4 v = vv[k];
                    if (v.x | v.y | v.z | v.w) {
                        int lb = (tid + k * 256) * 4;
                        unsigned m[4] = {v.x, v.y, v.z, v.w};
                        #pragma unroll
                        for (int c = 0; c < 4; c++) {
                            if (m[c]) {
                                int lit = lb + c;
                                int p = atomicAdd(&s_cnt[r], 1);
                                if (p < SCAPC) s_list[r * SCAPC + p] = lit;
                                int q = atomicAdd(&g_litCnt[lit], 1);
                                if (q < LCAP) g_litList[(size_t)lit * LCAP + q] = c0 + r;
                            }
                        }
                    }
                }
            }
        }
        __syncthreads();

        // gather g_LT over smem clause lists
        int cnts[16];
        #pragma unroll 1
        for (int cc = 0; cc < 16; cc++) {
            int cnt = min(s_cnt[cc], SCAPC);
            cnts[cc] = cnt;
            const int* lst = s_list + cc * SCAPC;
            float m0 = 0.f, m1 = 0.f, m2 = 0.f, m3 = 0.f;
            float m4 = 0.f, m5 = 0.f, m6 = 0.f, m7 = 0.f;
            int i = 0;
            for (; i + 7 < cnt; i += 8) {
                m0 += __ldg(&g_LT[(size_t)lst[i]     * BD + tid]);
                m1 += __ldg(&g_LT[(size_t)lst[i + 1] * BD + tid]);
                m2 += __ldg(&g_LT[(size_t)lst[i + 2] * BD + tid]);
                m3 += __ldg(&g_LT[(size_t)lst[i + 3] * BD + tid]);
                m4 += __ldg(&g_LT[(size_t)lst[i + 4] * BD + tid]);
                m5 += __ldg(&g_LT[(size_t)lst[i + 5] * BD + tid]);
                m6 += __ldg(&g_LT[(size_t)lst[i + 6] * BD + tid]);
                m7 += __ldg(&g_LT[(size_t)lst[i + 7] * BD + tid]);
            }
            for (; i < cnt; i++) m0 += __ldg(&g_LT[(size_t)lst[i] * BD + tid]);
            s_S[tid * 20 + cc] = ((m0 + m1) + (m2 + m3)) + ((m4 + m5) + (m6 + m7));
        }
        __syncthreads();

        // matvec: WCu1 @ ct + Wcm @ S + bCu + cnt*bcm
        int b = tid >> 6, ch = tid & 63;
        unsigned long long acc2[8];
        #pragma unroll
        for (int i = 0; i < 8; i++) acc2[i] = 0ull;
        const float4* w1 = (const float4*)(WCu + ch * 128);
        const float4* w2 = (const float4*)(g_Wcm + ch * 64);
        #pragma unroll 4
        for (int j4 = 0; j4 < 16; j4++) {
            float4 wv = __ldg(&w1[j4]);
            const float* x = s_ct + (b * 64 + j4 * 4) * 20;
            FMA16P(acc2, wv.x, x);
            FMA16P(acc2, wv.y, x + 20);
            FMA16P(acc2, wv.z, x + 40);
            FMA16P(acc2, wv.w, x + 60);
        }
        #pragma unroll 4
        for (int j4 = 0; j4 < 16; j4++) {
            float4 wv = __ldg(&w2[j4]);
            const float* x = s_S + (b * 64 + j4 * 4) * 20;
            FMA16P(acc2, wv.x, x);
            FMA16P(acc2, wv.y, x + 20);
            FMA16P(acc2, wv.z, x + 40);
            FMA16P(acc2, wv.w, x + 60);
        }
        float acc[16];
        UNPACK16(acc, acc2);

        float bb = __ldg(&bCu[ch]), bc = __ldg(&g_bcm[ch]);
        float lsum = 0.f;
        #pragma unroll
        for (int cc = 0; cc < 16; cc++) {
            float v = leaky(acc[cc] + bb + (float)cnts[cc] * bc);
            acc[cc] = v;
            lsum += v;
            g_CnewT[(size_t)(c0 + cc) * BD + tid] = v;
        }
        float4* orow = (float4*)(outC + (size_t)tid * NC + c0);
        orow[0] = make_float4(acc[0], acc[1], acc[2], acc[3]);
        orow[1] = make_float4(acc[4], acc[5], acc[6], acc[7]);
        orow[2] = make_float4(acc[8], acc[9], acc[10], acc[11]);
        orow[3] = make_float4(acc[12], acc[13], acc[14], acc[15]);
        atomicAdd(&g_sumC[tid], lsum);
    } else {
        // P tile: WLu1 @ L + WLu3 @ L_flip + bLu — two-pass over one buffer
        float* s_X = smem_buf;   // 256*20
        int l0 = p_id * 16;
        int lf0 = (l0 + 4096) & (NL - 1);
        for (int idx = tid; idx < 256 * 16; idx += 256) {
            int r = idx >> 4, cc = idx & 15;
            s_X[r * 20 + cc] = L[(size_t)r * NL + l0 + cc];
        }
        __syncthreads();
        int b = tid >> 6, ch = tid & 63;
        unsigned long long acc2[8];
        #pragma unroll
        for (int i = 0; i < 8; i++) acc2[i] = 0ull;
        const float4* w1 = (const float4*)(WLu + ch * 192);
        const float4* w3 = (const float4*)(WLu + ch * 192 + 128);
        #pragma unroll 4
        for (int j4 = 0; j4 < 16; j4++) {
            float4 wv = __ldg(&w1[j4]);
            const float* x = s_X + (b * 64 + j4 * 4) * 20;
            FMA16P(acc2, wv.x, x);
            FMA16P(acc2, wv.y, x + 20);
            FMA16P(acc2, wv.z, x + 40);
            FMA16P(acc2, wv.w, x + 60);
        }
        __syncthreads();
        for (int idx = tid; idx < 256 * 16; idx += 256) {
            int r = idx >> 4, cc = idx & 15;
            s_X[r * 20 + cc] = L[(size_t)r * NL + lf0 + cc];
        }
        __syncthreads();
        #pragma unroll 4
        for (int j4 = 0; j4 < 16; j4++) {
            float4 wv = __ldg(&w3[j4]);
            const float* x = s_X + (b * 64 + j4 * 4) * 20;
            FMA16P(acc2, wv.x, x);
            FMA16P(acc2, wv.y, x + 20);
            FMA16P(acc2, wv.z, x + 40);
            FMA16P(acc2, wv.w, x + 60);
        }
        float acc[16];
        UNPACK16(acc, acc2);
        float bb = __ldg(&bLu[ch]);
        #pragma unroll
        for (int cc = 0; cc < 16; cc++)
            g_P[(size_t)(l0 + cc) * BD + tid] = acc[cc] + bb;
    }
}

// Literal update: gather C_new + Wcl matvec + P.
__global__ __launch_bounds__(256) void k_literalUp(float* __restrict__ outL) {
    extern __shared__ float sm[];
    float* s_S   = sm;                     // 256*20
    int*   s_cnt = (int*)(s_S + 256 * 20); // 16
    int*   s_list = s_cnt + 16;            // 16*LCAP

    int tid = threadIdx.x;
    int l0 = blockIdx.x * 16;

    if (tid < 16) s_cnt[tid] = min(g_litCnt[l0 + tid], LCAP);
    __syncthreads();
    for (int idx = tid; idx < 16 * LCAP; idx += 256) {
        int cc = idx >> 6, i = idx & 63;
        if (i < s_cnt[cc]) s_list[idx] = g_litList[(size_t)(l0 + cc) * LCAP + i];
    }
    __syncthreads();

    #pragma unroll 1
    for (int cc = 0; cc < 16; cc++) {
        int cnt = s_cnt[cc];
        const int* lst = s_list + cc * LCAP;
        float m0 = 0.f, m1 = 0.f, m2 = 0.f, m3 = 0.f;
        float m4 = 0.f, m5 = 0.f, m6 = 0.f, m7 = 0.f;
        int i = 0;
        for (; i + 7 < cnt; i += 8) {
            m0 += __ldg(&g_CnewT[(size_t)lst[i]     * BD + tid]);
            m1 += __ldg(&g_CnewT[(size_t)lst[i + 1] * BD + tid]);
            m2 += __ldg(&g_CnewT[(size_t)lst[i + 2] * BD + tid]);
            m3 += __ldg(&g_CnewT[(size_t)lst[i + 3] * BD + tid]);
            m4 += __ldg(&g_CnewT[(size_t)lst[i + 4] * BD + tid]);
            m5 += __ldg(&g_CnewT[(size_t)lst[i + 5] * BD + tid]);
            m6 += __ldg(&g_CnewT[(size_t)lst[i + 6] * BD + tid]);
            m7 += __ldg(&g_CnewT[(size_t)lst[i + 7] * BD + tid]);
        }
        for (; i < cnt; i++) m0 += __ldg(&g_CnewT[(size_t)lst[i] * BD + tid]);
        s_S[tid * 20 + cc] = ((m0 + m1) + (m2 + m3)) + ((m4 + m5) + (m6 + m7));
    }
    __syncthreads();

    int b = tid >> 6, ch = tid & 63;
    unsigned long long acc2[8];
    #pragma unroll
    for (int i = 0; i < 8; i++) acc2[i] = 0ull;
    const float4* wl = (const float4*)(g_Wcl + ch * 64);
    #pragma unroll 4
    for (int j4 = 0; j4 < 16; j4++) {
        float4 wv = __ldg(&wl[j4]);
        const float* x = s_S + (b * 64 + j4 * 4) * 20;
        FMA16P(acc2, wv.x, x);
        FMA16P(acc2, wv.y, x + 20);
        FMA16P(acc2, wv.z, x + 40);
        FMA16P(acc2, wv.w, x + 60);
    }
    float acc[16];
    UNPACK16(acc, acc2);

    float bc = __ldg(&g_bcl[ch]);
    float lsum = 0.f;
    #pragma unroll
    for (int cc = 0; cc < 16; cc++) {
        float p = __ldg(&g_P[(size_t)(l0 + cc) * BD + tid]);
        float v = leaky(acc[cc] + p + (float)s_cnt[cc] * bc);
        acc[cc] = v;
        lsum += v;
    }
    float4* orow = (float4*)(outL + (size_t)tid * NL + l0);
    orow[0] = make_float4(acc[0], acc[1], acc[2], acc[3]);
    orow[1] = make_float4(acc[4], acc[5], acc[6], acc[7]);
    orow[2] = make_float4(acc[8], acc[9], acc[10], acc[11]);
    orow[3] = make_float4(acc[12], acc[13], acc[14], acc[15]);
    atomicAdd(&g_sumL[tid], lsum);
}

__global__ void k_U(const float* __restrict__ U, const float* __restrict__ WUu,
                    const float* __restrict__ bUu, float* __restrict__ out) {
    __shared__ float glb[4 * 192];
    int tid = threadIdx.x;
    int b = tid >> 6, ch = tid & 63;
    glb[b * 192 + ch]       = g_sumL[tid];
    glb[b * 192 + 64 + ch]  = g_sumC[tid];
    glb[b * 192 + 128 + ch] = U[tid];
    __syncthreads();
    float s = bUu[ch];
    #pragma unroll 8
    for (int i = 0; i < 192; i++) s += WUu[ch * 192 + i] * glb[b * 192 + i];
    out[tid] = leaky(s);
}

// ---------------- launch ----------------
extern "C" void kernel_launch(void* const* d_in, const int* in_sizes, int n_in,
                              void* d_out, int out_size) {
    const float* L     = (const float*)d_in[0];
    const float* C     = (const float*)d_in[1];
    const float* U     = (const float*)d_in[2];
    const float* A     = (const float*)d_in[3];
    const float* WLmsg = (const float*)d_in[5];
    const float* bLmsg = (const float*)d_in[6];
    const float* WCmsg = (const float*)d_in[7];
    const float* bCmsg = (const float*)d_in[8];
    const float* WLu   = (const float*)d_in[9];
    const float* bLu   = (const float*)d_in[10];
    const float* WCu   = (const float*)d_in[11];
    const float* bCu   = (const float*)d_in[12];
    const float* WUu   = (const float*)d_in[13];
    const float* bUu   = (const float*)d_in[14];
    float* out = (float*)d_out;

    const int smem_literal = (256 * 20 + 16 + 16 * LCAP) * 4;
    cudaFuncSetAttribute(k_literalUp, cudaFuncAttributeMaxDynamicSharedMemorySize, smem_literal);

    k_zero<<<64, 256>>>(WCu, WLmsg, bLmsg, WLu, WCmsg, bCmsg);
    k_prep<<<NL / 32, 256>>>(L);
    k_mega2<<<MEGA2_BLOCKS, 256>>>((const uint4*)A, L, C, WCu, WLu, bCu, bLu, out + OUT_C);
    k_literalUp<<<NL / 16, 256, smem_literal>>>(out + OUT_L);
    k_U<<<1, 256>>>(U, WUu, bUu, out + OUT_U);
}